// round 1
// baseline (speedup 1.0000x reference)
#include <cuda_runtime.h>
#include <math.h>

// ---------------------------------------------------------------------------
// Problem constants
// ---------------------------------------------------------------------------
#define BB 16
#define TT 7
#define NN 2048
#define DD 128
#define M1 (BB*TT*NN)   /* 229376 rows of the big GEMMs */
#define M0 (BB*NN)      /* 32768 rows of the STE GEMM   */

// ---------------------------------------------------------------------------
// Device scratch (no allocation allowed at runtime)
// ---------------------------------------------------------------------------
__device__ float g_W1[128*384];          // X-part of packed qkv weights   [k][j]
__device__ float g_W2[128*384];          // STE-part of packed qkv weights [k][j]
__device__ float g_bias[384];            // packed bq|bk|bv
__device__ float g_ste[M0*384];          // STE@W2 + bias per (b,n)        ~50MB
__device__ float g_y[M1*384];            // pre-BN q|k|v                   ~352MB
__device__ float g_attout[M1*128];       // attention output               ~117MB
__device__ float g_opre[M1*128];         // pre-BN o                       ~117MB
__device__ float g_stats[1024];          // [0:512) sums, [512:1024) sumsqs
__device__ float g_bnscale[512];         // 0..383 qkv, 384..511 o
__device__ float g_bnshift[512];

__device__ __forceinline__ float gelu_f(float x) {
    return 0.5f * x * (1.0f + erff(x * 0.70710678118654752f));
}

// ---------------------------------------------------------------------------
// Utility kernels
// ---------------------------------------------------------------------------
__global__ void zero_stats_kernel() {
    g_stats[threadIdx.x] = 0.0f;   // <<<1,1024>>>
}

__global__ void pack_weights_kernel(const float* __restrict__ wq, const float* __restrict__ bq,
                                    const float* __restrict__ wk, const float* __restrict__ bk,
                                    const float* __restrict__ wv, const float* __restrict__ bv) {
    int idx = blockIdx.x * blockDim.x + threadIdx.x;
    if (idx >= 128*384) return;
    int k = idx / 384;
    int j = idx - k*384;
    int sel = j >> 7;
    int jj = j & 127;
    const float* w = (sel == 0) ? wq : (sel == 1) ? wk : wv;
    g_W1[k*384 + j] = w[k*128 + jj];           // rows 0..127   (X part)
    g_W2[k*384 + j] = w[(k+128)*128 + jj];     // rows 128..255 (STE part)
    if (k == 0) {
        const float* bb = (sel == 0) ? bq : (sel == 1) ? bk : bv;
        g_bias[j] = bb[jj];
    }
}

// ---------------------------------------------------------------------------
// Generic 128x128x128 fp32 GEMM with fused epilogue.
// MODE bit0: add bias[j]; bit1: add STE row (row mapping m -> b*NN + n);
// MODE bit2: accumulate per-channel sum/sumsq into stats.
// A: [gridDim.x*128, 128] row-major.  W: [128, *] row stride wstride.
// C: [.., cstride] row-major, this block writes cols j0..j0+127.
// ---------------------------------------------------------------------------
#define SP 132
#define GEMM_SMEM (2*128*SP*sizeof(float))

template<int MODE>
__global__ void __launch_bounds__(256, 1)
gemm128_kernel(const float* __restrict__ A, const float* __restrict__ W, int wstride,
               const float* __restrict__ bias, const float* __restrict__ addv,
               float* __restrict__ C, int cstride,
               float* __restrict__ stats, int statsOff)
{
    extern __shared__ float smem[];
    float* As = smem;             // As[k*SP + m]
    float* Ws = smem + 128*SP;    // Ws[k*SP + j]

    const int tid = threadIdx.x;
    const int tx = tid & 15, ty = tid >> 4;
    const int m0 = blockIdx.x * 128;
    const int j0 = blockIdx.y * 128;

    // Load both 128x128 tiles (A transposed into As).
    #pragma unroll
    for (int i = 0; i < 16; i++) {
        int f  = tid + i*256;          // 0..4095
        int r  = f >> 5;               // row / k-row (0..127)
        int jj = (f & 31) << 2;        // 0..124 step 4
        *(float4*)(Ws + r*SP + jj) = *(const float4*)(W + (size_t)r*wstride + j0 + jj);
        float4 a4 = *(const float4*)(A + (size_t)(m0 + r)*128 + jj);
        As[(jj+0)*SP + r] = a4.x;
        As[(jj+1)*SP + r] = a4.y;
        As[(jj+2)*SP + r] = a4.z;
        As[(jj+3)*SP + r] = a4.w;
    }
    __syncthreads();

    float acc[8][8];
    #pragma unroll
    for (int i = 0; i < 8; i++)
        #pragma unroll
        for (int q = 0; q < 8; q++) acc[i][q] = 0.0f;

    #pragma unroll 2
    for (int k = 0; k < 128; k++) {
        float4 a0 = *(const float4*)(As + k*SP + (ty<<2));
        float4 a1 = *(const float4*)(As + k*SP + 64 + (ty<<2));
        float4 b0 = *(const float4*)(Ws + k*SP + (tx<<2));
        float4 b1 = *(const float4*)(Ws + k*SP + 64 + (tx<<2));
        float af[8] = {a0.x,a0.y,a0.z,a0.w, a1.x,a1.y,a1.z,a1.w};
        float bf[8] = {b0.x,b0.y,b0.z,b0.w, b1.x,b1.y,b1.z,b1.w};
        #pragma unroll
        for (int i = 0; i < 8; i++)
            #pragma unroll
            for (int q = 0; q < 8; q++)
                acc[i][q] = fmaf(af[i], bf[q], acc[i][q]);
    }

    float colsum[8], colsq[8];
    #pragma unroll
    for (int q = 0; q < 8; q++) { colsum[q] = 0.0f; colsq[q] = 0.0f; }

    float bvals[8];
    if (MODE & 1) {
        #pragma unroll
        for (int q = 0; q < 8; q++) {
            int c = (q < 4) ? (tx<<2)+q : 64+(tx<<2)+(q-4);
            bvals[q] = bias[j0 + c];
        }
    }

    #pragma unroll
    for (int i = 0; i < 8; i++) {
        int r = (i < 4) ? (ty<<2)+i : 64+(ty<<2)+(i-4);
        int m = m0 + r;
        const float* srow = nullptr;
        if (MODE & 2) {
            int b = m / (TT*NN);
            int n = m & (NN - 1);
            srow = addv + (size_t)(b*NN + n)*384 + j0;
        }
        #pragma unroll
        for (int q = 0; q < 8; q++) {
            int c = (q < 4) ? (tx<<2)+q : 64+(tx<<2)+(q-4);
            float v = acc[i][q];
            if (MODE & 1) v += bvals[q];
            if (MODE & 2) v += srow[c];
            C[(size_t)m*cstride + j0 + c] = v;
            if (MODE & 4) { colsum[q] += v; colsq[q] += v*v; }
        }
    }

    if (MODE & 4) {
        __syncthreads();                 // done reading As/Ws
        float* sred = smem;
        float* srq  = smem + 128;
        if (tid < 128) { sred[tid] = 0.0f; srq[tid] = 0.0f; }
        __syncthreads();
        #pragma unroll
        for (int q = 0; q < 8; q++) {
            int c = (q < 4) ? (tx<<2)+q : 64+(tx<<2)+(q-4);
            atomicAdd(&sred[c], colsum[q]);
            atomicAdd(&srq[c],  colsq[q]);
        }
        __syncthreads();
        if (tid < 128) {
            atomicAdd(&stats[statsOff + j0 + tid],       sred[tid]);
            atomicAdd(&stats[512 + statsOff + j0 + tid], srq[tid]);
        }
    }
}

// ---------------------------------------------------------------------------
// BN affine params from accumulated stats
// ---------------------------------------------------------------------------
__global__ void bn_params_kernel(const float* __restrict__ stats, int off,
                                 const float* __restrict__ gamma, const float* __restrict__ beta,
                                 float* __restrict__ scale, float* __restrict__ shift,
                                 int outOff, float invM)
{
    int c = threadIdx.x;   // <<<1,128>>>
    float s  = stats[off + c];
    float sq = stats[512 + off + c];
    float mu  = s * invM;
    float var = sq * invM - mu*mu;
    float rs  = rsqrtf(var + 1e-5f);
    float sc  = gamma[c] * rs;
    scale[outOff + c] = sc;
    shift[outOff + c] = beta[c] - mu * sc;
}

// ---------------------------------------------------------------------------
// Fused BN+GELU(q,k,v) + 16-head dim-8 attention over T=7, per (b,n).
// ---------------------------------------------------------------------------
__global__ void __launch_bounds__(128)
attn_kernel(const float* __restrict__ y, const float* __restrict__ scale,
            const float* __restrict__ shift, float* __restrict__ att_out)
{
    __shared__ float qkv[7][384];
    __shared__ float obuf[7][128];

    int bn  = blockIdx.x;
    int b   = bn >> 11;
    int n   = bn & (NN - 1);
    int tid = threadIdx.x;

    #pragma unroll
    for (int t = 0; t < 7; t++) {
        const float* row = y + (size_t)((b*7 + t)*NN + n)*384;
        #pragma unroll
        for (int it = 0; it < 3; it++) {
            int idx = tid + it*128;
            float v = row[idx]*scale[idx] + shift[idx];
            qkv[t][idx] = gelu_f(v);
        }
    }
    __syncthreads();

    if (tid < 112) {
        int h = tid / 7;
        int t = tid - h*7;
        int off = h*8;
        float s[7], mx = -1e30f;
        #pragma unroll
        for (int j = 0; j < 7; j++) {
            float dsum = 0.0f;
            #pragma unroll
            for (int c = 0; c < 8; c++) dsum += qkv[t][off+c] * qkv[j][128+off+c];
            s[j] = dsum * 0.25f;                         // / sqrt(16)
            mx = fmaxf(mx, s[j]);
        }
        float ssum = 0.0f;
        #pragma unroll
        for (int j = 0; j < 7; j++) { s[j] = __expf(s[j]-mx); ssum += s[j]; }
        float inv = 1.0f / ssum;
        float o[8];
        #pragma unroll
        for (int c = 0; c < 8; c++) o[c] = 0.0f;
        #pragma unroll
        for (int j = 0; j < 7; j++) {
            float p = s[j] * inv;
            #pragma unroll
            for (int c = 0; c < 8; c++) o[c] += p * qkv[j][256+off+c];
        }
        #pragma unroll
        for (int c = 0; c < 8; c++) obuf[t][off+c] = o[c];
    }
    __syncthreads();

    #pragma unroll
    for (int t = 0; t < 7; t++)
        att_out[(size_t)((b*7 + t)*NN + n)*128 + tid] = obuf[t][tid];
}

// ---------------------------------------------------------------------------
// Final: BN+GELU(o) fused with Linear(7->1) over time
// ---------------------------------------------------------------------------
__global__ void final_kernel(const float* __restrict__ opre, const float* __restrict__ lw,
                             const float* __restrict__ lb, const float* __restrict__ scale,
                             const float* __restrict__ shift, float* __restrict__ out)
{
    int idx = blockIdx.x*blockDim.x + threadIdx.x;
    if (idx >= BB*NN*DD) return;
    int d = idx & 127;
    int n = (idx >> 7) & (NN - 1);
    int b = idx >> 18;
    float sc = scale[d], sh = shift[d];
    float acc = lb[0];
    #pragma unroll
    for (int t = 0; t < 7; t++) {
        float v = opre[(size_t)((b*7 + t)*NN + n)*128 + d];
        acc += gelu_f(v*sc + sh) * lw[t];
    }
    out[idx] = acc;
}

// ---------------------------------------------------------------------------
// Launcher
// ---------------------------------------------------------------------------
extern "C" void kernel_launch(void* const* d_in, const int* in_sizes, int n_in,
                              void* d_out, int out_size)
{
    const float* X   = (const float*)d_in[0];
    const float* STE = (const float*)d_in[1];
    const float* wq  = (const float*)d_in[2];
    const float* bq  = (const float*)d_in[3];
    const float* gq  = (const float*)d_in[4];
    const float* btq = (const float*)d_in[5];
    const float* wk  = (const float*)d_in[6];
    const float* bk  = (const float*)d_in[7];
    const float* gk  = (const float*)d_in[8];
    const float* btk = (const float*)d_in[9];
    const float* wv  = (const float*)d_in[10];
    const float* bv  = (const float*)d_in[11];
    const float* gv  = (const float*)d_in[12];
    const float* btv = (const float*)d_in[13];
    const float* wo  = (const float*)d_in[14];
    const float* bo  = (const float*)d_in[15];
    const float* go  = (const float*)d_in[16];
    const float* bto = (const float*)d_in[17];
    const float* lw  = (const float*)d_in[18];
    const float* lb  = (const float*)d_in[19];
    float* out = (float*)d_out;

    float *pW1, *pW2, *pBias, *pSte, *pY, *pAtt, *pOpre, *pStats, *pScale, *pShift;
    cudaGetSymbolAddress((void**)&pW1,    g_W1);
    cudaGetSymbolAddress((void**)&pW2,    g_W2);
    cudaGetSymbolAddress((void**)&pBias,  g_bias);
    cudaGetSymbolAddress((void**)&pSte,   g_ste);
    cudaGetSymbolAddress((void**)&pY,     g_y);
    cudaGetSymbolAddress((void**)&pAtt,   g_attout);
    cudaGetSymbolAddress((void**)&pOpre,  g_opre);
    cudaGetSymbolAddress((void**)&pStats, g_stats);
    cudaGetSymbolAddress((void**)&pScale, g_bnscale);
    cudaGetSymbolAddress((void**)&pShift, g_bnshift);

    cudaFuncSetAttribute(gemm128_kernel<1>, cudaFuncAttributeMaxDynamicSharedMemorySize, (int)GEMM_SMEM);
    cudaFuncSetAttribute(gemm128_kernel<6>, cudaFuncAttributeMaxDynamicSharedMemorySize, (int)GEMM_SMEM);
    cudaFuncSetAttribute(gemm128_kernel<5>, cudaFuncAttributeMaxDynamicSharedMemorySize, (int)GEMM_SMEM);

    const float invM = 1.0f / (float)M1;

    zero_stats_kernel<<<1, 1024>>>();
    pack_weights_kernel<<<(128*384 + 255)/256, 256>>>(wq, bq, wk, bk, wv, bv);

    // STE part of QKV FC: [32768,128] @ [128,384] + bias  -> g_ste
    gemm128_kernel<1><<<dim3(M0/128, 3), 256, GEMM_SMEM>>>(
        STE, pW2, 384, pBias, nullptr, pSte, 384, nullptr, 0);

    // X part + STE add + stats: [229376,128] @ [128,384]  -> g_y
    gemm128_kernel<6><<<dim3(M1/128, 3), 256, GEMM_SMEM>>>(
        X, pW1, 384, nullptr, pSte, pY, 384, pStats, 0);

    bn_params_kernel<<<1, 128>>>(pStats,   0, gq, btq, pScale, pShift,   0, invM);
    bn_params_kernel<<<1, 128>>>(pStats, 128, gk, btk, pScale, pShift, 128, invM);
    bn_params_kernel<<<1, 128>>>(pStats, 256, gv, btv, pScale, pShift, 256, invM);

    attn_kernel<<<M0, 128>>>(pY, pScale, pShift, pAtt);

    // O FC: [229376,128] @ [128,128] + bias + stats -> g_opre
    gemm128_kernel<5><<<dim3(M1/128, 1), 256, GEMM_SMEM>>>(
        pAtt, wo, 128, bo, nullptr, pOpre, 128, pStats, 384);

    bn_params_kernel<<<1, 128>>>(pStats, 384, go, bto, pScale, pShift, 384, invM);

    final_kernel<<<(BB*NN*DD + 255)/256, 256>>>(pOpre, lw, lb, pScale + 384, pShift + 384, out);
}

// round 4
// speedup vs baseline: 1.2525x; 1.2525x over previous
#include <cuda_runtime.h>
#include <cuda_bf16.h>
#include <math.h>
#include <cstdint>

// ---------------------------------------------------------------------------
// Problem constants
// ---------------------------------------------------------------------------
#define BB 16
#define TT 7
#define NN 2048
#define DD 128
#define M1 (BB*TT*NN)   /* 229376 */
#define M0 (BB*NN)      /* 32768  */

// ---------------------------------------------------------------------------
// mma.sync / ldmatrix helpers (generic sm_80+, works on compute_100)
// ---------------------------------------------------------------------------
__device__ __forceinline__ uint32_t smem_u32(const void* p) {
    uint32_t a;
    asm("{ .reg .u64 t; cvta.to.shared.u64 t, %1; cvt.u32.u64 %0, t; }" : "=r"(a) : "l"(p));
    return a;
}

#define LDM4(r, a) \
    asm volatile("ldmatrix.sync.aligned.m8n8.x4.shared.b16 {%0,%1,%2,%3}, [%4];" \
        : "=r"((r)[0]), "=r"((r)[1]), "=r"((r)[2]), "=r"((r)[3]) : "r"(a))

#define MMA16(c, a, b0_, b1_) \
    asm volatile("mma.sync.aligned.m16n8k16.row.col.f32.bf16.bf16.f32 " \
        "{%0,%1,%2,%3},{%4,%5,%6,%7},{%8,%9},{%0,%1,%2,%3};" \
        : "+f"((c)[0]), "+f"((c)[1]), "+f"((c)[2]), "+f"((c)[3]) \
        : "r"((a)[0]), "r"((a)[1]), "r"((a)[2]), "r"((a)[3]), "r"(b0_), "r"(b1_))

// ---------------------------------------------------------------------------
// Device scratch
// ---------------------------------------------------------------------------
__device__ __nv_bfloat16 g_Wb1[6 * 16384];   // QKV X-part: [jt*2+hl][n][k]
__device__ __nv_bfloat16 g_Wb2[6 * 16384];   // QKV STE-part
__device__ __nv_bfloat16 g_Wbo[2 * 16384];   // O weights
__device__ float g_bias[384];
__device__ float g_ste[(size_t)M0 * 384];
__device__ float g_y[(size_t)M1 * 384];
__device__ float g_attout[(size_t)M1 * 128];
__device__ float g_opre[(size_t)M1 * 128];
__device__ float g_stats[1024];
__device__ float g_bnscale[512];
__device__ float g_bnshift[512];

__device__ __forceinline__ float gelu_f(float x) {
    return 0.5f * x * (1.0f + erff(x * 0.70710678118654752f));
}

// ---------------------------------------------------------------------------
// Utility kernels
// ---------------------------------------------------------------------------
__global__ void zero_stats_kernel() { g_stats[threadIdx.x] = 0.0f; }

__global__ void pack_qkv_kernel(const float* __restrict__ wq, const float* __restrict__ bq,
                                const float* __restrict__ wk, const float* __restrict__ bk,
                                const float* __restrict__ wv, const float* __restrict__ bv) {
    int idx = blockIdx.x * blockDim.x + threadIdx.x;
    if (idx >= 3 * 128 * 128) return;
    int jt = idx >> 14;
    int n  = (idx >> 7) & 127;
    int k  = idx & 127;
    const float* w = (jt == 0) ? wq : (jt == 1) ? wk : wv;
    float v1 = w[k * 128 + n];
    float v2 = w[(k + 128) * 128 + n];
    __nv_bfloat16 h1 = __float2bfloat16(v1);
    __nv_bfloat16 h2 = __float2bfloat16(v2);
    g_Wb1[(jt * 2 + 0) * 16384 + n * 128 + k] = h1;
    g_Wb1[(jt * 2 + 1) * 16384 + n * 128 + k] = __float2bfloat16(v1 - __bfloat162float(h1));
    g_Wb2[(jt * 2 + 0) * 16384 + n * 128 + k] = h2;
    g_Wb2[(jt * 2 + 1) * 16384 + n * 128 + k] = __float2bfloat16(v2 - __bfloat162float(h2));
    if (k == 0) {
        const float* bb = (jt == 0) ? bq : (jt == 1) ? bk : bv;
        g_bias[jt * 128 + n] = bb[n];
    }
}

__global__ void pack_wo_kernel(const float* __restrict__ wo) {
    int idx = blockIdx.x * blockDim.x + threadIdx.x;
    if (idx >= 16384) return;
    int n = idx >> 7, k = idx & 127;
    float v = wo[k * 128 + n];
    __nv_bfloat16 h = __float2bfloat16(v);
    g_Wbo[n * 128 + k] = h;
    g_Wbo[16384 + n * 128 + k] = __float2bfloat16(v - __bfloat162float(h));
}

// ---------------------------------------------------------------------------
// bf16 split-3 tensor-core GEMM via mma.sync.
//   C[m0:m0+128, 0:NJT*128] = A[m0:m0+128, 0:128] @ Bp^T (+bias)(+ste)(+stats)
//   A fp32 row-major (stride 128). Bp: NJT j-tiles, each hi+lo bf16 [n][k].
//   8 warps: 2(m) x 4(n), warp tile 64x32, mma m16n8k16.
// SMEM layout (bytes):
//   A_hi 0..34816, A_lo ..69632, B_hi ..104448, B_lo ..139264,
//   [ste 139264..206848 if STEADD], stats last 1024.
// ---------------------------------------------------------------------------
template<bool STEADD>
static constexpr int hg_smem() { return 139264 + (STEADD ? 67584 : 0) + 1024; }

template<int NJT, bool STEADD, bool STATS, bool BIASF, bool QKVMAP>
__global__ void __launch_bounds__(256, 1)
hgemm_kernel(const float* __restrict__ A, const __nv_bfloat16* __restrict__ Bp,
             const float* __restrict__ bias, const float* __restrict__ steg,
             float* __restrict__ C, float* __restrict__ stats, int statsOff)
{
    constexpr int NC = NJT * 128;
    constexpr int A_LO = 34816, B_HI = 69632, B_LO = 104448;
    constexpr int STE_OFF = 139264;
    constexpr int ST_OFF  = STEADD ? 206848 : 139264;

    extern __shared__ char sm[];
    const uint32_t sb = smem_u32(sm);

    const int tid  = threadIdx.x;
    const int lane = tid & 31;
    const int wid  = tid >> 5;
    const int wm   = wid >> 2;      // 0..1
    const int wn   = wid & 3;       // 0..3

    int m0, sterow0 = 0;
    if (QKVMAP) {
        int bx = blockIdx.x;
        int t = bx % 7, u = bx / 7;
        int nblk = u & 15, b = u >> 4;
        m0 = (b * 7 + t) * NN + nblk * 128;
        sterow0 = b * NN + nblk * 128;
    } else {
        m0 = blockIdx.x * 128;
    }

    // ---- load A tile, split fp32 -> bf16 hi/lo into padded smem (stride 136) ----
    {
        const float* Ag = A + (size_t)m0 * 128;
        #pragma unroll
        for (int i = 0; i < 16; i++) {
            int f  = tid + i * 256;       // 0..4095 float4s
            int r  = f >> 5;
            int c4 = (f & 31) << 2;
            float4 v = *(const float4*)(Ag + (size_t)r * 128 + c4);
            __nv_bfloat16 hx = __float2bfloat16(v.x);
            __nv_bfloat16 hy = __float2bfloat16(v.y);
            __nv_bfloat16 hz = __float2bfloat16(v.z);
            __nv_bfloat16 hw = __float2bfloat16(v.w);
            __nv_bfloat162 hp0; hp0.x = hx; hp0.y = hy;
            __nv_bfloat162 hp1; hp1.x = hz; hp1.y = hw;
            uint2 hv; hv.x = *(uint32_t*)&hp0; hv.y = *(uint32_t*)&hp1;
            __nv_bfloat162 lp0, lp1;
            lp0.x = __float2bfloat16(v.x - __bfloat162float(hx));
            lp0.y = __float2bfloat16(v.y - __bfloat162float(hy));
            lp1.x = __float2bfloat16(v.z - __bfloat162float(hz));
            lp1.y = __float2bfloat16(v.w - __bfloat162float(hw));
            uint2 lv; lv.x = *(uint32_t*)&lp0; lv.y = *(uint32_t*)&lp1;
            *(uint2*)(sm + r * 272 + c4 * 2)        = hv;
            *(uint2*)(sm + A_LO + r * 272 + c4 * 2) = lv;
        }
    }

    const int gid = lane >> 2, tig = lane & 3;
    const uint32_t aBase = sb + (wm * 64 + (lane & 15)) * 272 + ((lane >> 4) & 1) * 16;
    const uint32_t bBase = sb + B_HI + (wn * 32 + (lane & 7) + ((lane >> 4) << 3)) * 272
                              + ((lane >> 3) & 1) * 16;

    #pragma unroll 1
    for (int jt = 0; jt < NJT; jt++) {
        __syncthreads();   // previous epilogue done before overwriting B/ste/stats

        // ---- load B j-tile (hi+lo) into padded smem ----
        {
            const __nv_bfloat16* Bg = Bp + (size_t)jt * 2 * 16384;
            #pragma unroll
            for (int i = 0; i < 16; i++) {
                int f  = tid + i * 256;      // 0..4095 uint4s
                int hl = f >> 11;
                int g  = f & 2047;
                int r  = g >> 4;
                int ch = g & 15;
                uint4 val = ((const uint4*)(Bg + hl * 16384))[r * 16 + ch];
                *(uint4*)(sm + B_HI + hl * 34816 + r * 272 + ch * 16) = val;
            }
        }
        if (STEADD) {
            #pragma unroll
            for (int i = 0; i < 16; i++) {
                int f  = tid + i * 256;
                int r  = f >> 5;
                int c4 = (f & 31) << 2;
                float4 v = *(const float4*)(steg + (size_t)(sterow0 + r) * 384 + jt * 128 + c4);
                *(float4*)(sm + STE_OFF + r * 528 + c4 * 4) = v;
            }
        }
        if (STATS && tid < 128) {
            ((float*)(sm + ST_OFF))[tid] = 0.0f;
            ((float*)(sm + ST_OFF))[tid + 128] = 0.0f;
        }
        __syncthreads();

        // ---- mainloop: K=128 in 8 steps of k16, 3 split terms ----
        float acc[4][4][4];
        #pragma unroll
        for (int i = 0; i < 4; i++)
            #pragma unroll
            for (int j = 0; j < 4; j++)
                #pragma unroll
                for (int q = 0; q < 4; q++) acc[i][j][q] = 0.0f;

        #pragma unroll
        for (int kb = 0; kb < 8; kb++) {
            const int kby = kb * 32;
            uint32_t ah[4][4], al[4][4], bh[2][4], bl[2][4];
            #pragma unroll
            for (int mf = 0; mf < 4; mf++) LDM4(ah[mf], aBase + mf * 4352 + kby);
            #pragma unroll
            for (int mf = 0; mf < 4; mf++) LDM4(al[mf], aBase + A_LO + mf * 4352 + kby);
            #pragma unroll
            for (int g2 = 0; g2 < 2; g2++) LDM4(bh[g2], bBase + g2 * 4352 + kby);
            #pragma unroll
            for (int g2 = 0; g2 < 2; g2++) LDM4(bl[g2], bBase + 34816 + g2 * 4352 + kby);

            #pragma unroll
            for (int mf = 0; mf < 4; mf++)
                #pragma unroll
                for (int ng = 0; ng < 4; ng++) {
                    int g = ng >> 1, o = (ng & 1) * 2;
                    MMA16(acc[mf][ng], ah[mf], bh[g][o], bh[g][o + 1]);
                }
            #pragma unroll
            for (int mf = 0; mf < 4; mf++)
                #pragma unroll
                for (int ng = 0; ng < 4; ng++) {
                    int g = ng >> 1, o = (ng & 1) * 2;
                    MMA16(acc[mf][ng], ah[mf], bl[g][o], bl[g][o + 1]);
                }
            #pragma unroll
            for (int mf = 0; mf < 4; mf++)
                #pragma unroll
                for (int ng = 0; ng < 4; ng++) {
                    int g = ng >> 1, o = (ng & 1) * 2;
                    MMA16(acc[mf][ng], al[mf], bh[g][o], bh[g][o + 1]);
                }
        }

        // ---- epilogue ----
        float csum[8], csq[8];
        #pragma unroll
        for (int i = 0; i < 8; i++) { csum[i] = 0.0f; csq[i] = 0.0f; }

        float2 bb[4];
        #pragma unroll
        for (int ng = 0; ng < 4; ng++) {
            if (BIASF) bb[ng] = *(const float2*)(bias + jt * 128 + wn * 32 + ng * 8 + tig * 2);
            else       bb[ng] = make_float2(0.0f, 0.0f);
        }

        #pragma unroll
        for (int mf = 0; mf < 4; mf++) {
            int mloc0 = wm * 64 + mf * 16 + gid;
            #pragma unroll
            for (int ng = 0; ng < 4; ng++) {
                int nloc = wn * 32 + ng * 8 + tig * 2;
                int jcol = jt * 128 + nloc;
                #pragma unroll
                for (int h = 0; h < 2; h++) {
                    int mloc = mloc0 + h * 8;
                    float v0 = acc[mf][ng][h * 2 + 0] + bb[ng].x;
                    float v1 = acc[mf][ng][h * 2 + 1] + bb[ng].y;
                    if (STEADD) {
                        float2 ss = *(float2*)(sm + STE_OFF + mloc * 528 + nloc * 4);
                        v0 += ss.x; v1 += ss.y;
                    }
                    *(float2*)(C + (size_t)(m0 + mloc) * NC + jcol) = make_float2(v0, v1);
                    if (STATS) {
                        csum[ng * 2 + 0] += v0; csq[ng * 2 + 0] += v0 * v0;
                        csum[ng * 2 + 1] += v1; csq[ng * 2 + 1] += v1 * v1;
                    }
                }
            }
        }

        if (STATS) {
            float* ssum = (float*)(sm + ST_OFF);
            float* ssq  = ssum + 128;
            #pragma unroll
            for (int ng = 0; ng < 4; ng++) {
                #pragma unroll
                for (int h2 = 0; h2 < 2; h2++) {
                    int nl = wn * 32 + ng * 8 + tig * 2 + h2;
                    atomicAdd(&ssum[nl], csum[ng * 2 + h2]);
                    atomicAdd(&ssq[nl],  csq[ng * 2 + h2]);
                }
            }
            __syncthreads();
            if (tid < 128) {
                atomicAdd(&stats[statsOff + jt * 128 + tid],       ssum[tid]);
                atomicAdd(&stats[512 + statsOff + jt * 128 + tid], ssq[tid]);
            }
        }
    }
}

// ---------------------------------------------------------------------------
// BN affine params
// ---------------------------------------------------------------------------
__global__ void bn_params_kernel(const float* __restrict__ stats, int off,
                                 const float* __restrict__ gamma, const float* __restrict__ beta,
                                 float* __restrict__ scale, float* __restrict__ shift,
                                 int outOff, float invM)
{
    int c = threadIdx.x;
    float s  = stats[off + c];
    float sq = stats[512 + off + c];
    float mu  = s * invM;
    float var = sq * invM - mu * mu;
    float rs  = rsqrtf(var + 1e-5f);
    float sc  = gamma[c] * rs;
    scale[outOff + c] = sc;
    shift[outOff + c] = beta[c] - mu * sc;
}

// ---------------------------------------------------------------------------
// Fused BN+GELU(q,k,v) + 16-head dim-8 attention over T=7, per (b,n)
// ---------------------------------------------------------------------------
__global__ void __launch_bounds__(128)
attn_kernel(const float* __restrict__ y, const float* __restrict__ scale,
            const float* __restrict__ shift, float* __restrict__ att_out)
{
    __shared__ float qkv[7][384];
    __shared__ float obuf[7][128];

    int bn  = blockIdx.x;
    int b   = bn >> 11;
    int n   = bn & (NN - 1);
    int tid = threadIdx.x;

    #pragma unroll
    for (int t = 0; t < 7; t++) {
        const float* row = y + (size_t)((b * 7 + t) * NN + n) * 384;
        #pragma unroll
        for (int it = 0; it < 3; it++) {
            int idx = tid + it * 128;
            float v = row[idx] * scale[idx] + shift[idx];
            qkv[t][idx] = gelu_f(v);
        }
    }
    __syncthreads();

    if (tid < 112) {
        int h = tid / 7;
        int t = tid - h * 7;
        int off = h * 8;
        float s[7], mx = -1e30f;
        #pragma unroll
        for (int j = 0; j < 7; j++) {
            float dsum = 0.0f;
            #pragma unroll
            for (int c = 0; c < 8; c++) dsum += qkv[t][off + c] * qkv[j][128 + off + c];
            s[j] = dsum * 0.25f;
            mx = fmaxf(mx, s[j]);
        }
        float ssum = 0.0f;
        #pragma unroll
        for (int j = 0; j < 7; j++) { s[j] = __expf(s[j] - mx); ssum += s[j]; }
        float inv = 1.0f / ssum;
        float o[8];
        #pragma unroll
        for (int c = 0; c < 8; c++) o[c] = 0.0f;
        #pragma unroll
        for (int j = 0; j < 7; j++) {
            float p = s[j] * inv;
            #pragma unroll
            for (int c = 0; c < 8; c++) o[c] += p * qkv[j][256 + off + c];
        }
        #pragma unroll
        for (int c = 0; c < 8; c++) obuf[t][off + c] = o[c];
    }
    __syncthreads();

    #pragma unroll
    for (int t = 0; t < 7; t++)
        att_out[(size_t)((b * 7 + t) * NN + n) * 128 + tid] = obuf[t][tid];
}

// ---------------------------------------------------------------------------
// Final: BN+GELU(o) fused with Linear(7->1) over time
// ---------------------------------------------------------------------------
__global__ void final_kernel(const float* __restrict__ opre, const float* __restrict__ lw,
                             const float* __restrict__ lb, const float* __restrict__ scale,
                             const float* __restrict__ shift, float* __restrict__ out)
{
    int idx = blockIdx.x * blockDim.x + threadIdx.x;
    if (idx >= BB * NN * DD) return;
    int d = idx & 127;
    int n = (idx >> 7) & (NN - 1);
    int b = idx >> 18;
    float sc = scale[d], sh = shift[d];
    float acc = lb[0];
    #pragma unroll
    for (int t = 0; t < 7; t++) {
        float v = opre[(size_t)((b * 7 + t) * NN + n) * 128 + d];
        acc += gelu_f(v * sc + sh) * lw[t];
    }
    out[idx] = acc;
}

// ---------------------------------------------------------------------------
// Launcher
// ---------------------------------------------------------------------------
extern "C" void kernel_launch(void* const* d_in, const int* in_sizes, int n_in,
                              void* d_out, int out_size)
{
    const float* X   = (const float*)d_in[0];
    const float* STE = (const float*)d_in[1];
    const float* wq  = (const float*)d_in[2];
    const float* bq  = (const float*)d_in[3];
    const float* gq  = (const float*)d_in[4];
    const float* btq = (const float*)d_in[5];
    const float* wk  = (const float*)d_in[6];
    const float* bk  = (const float*)d_in[7];
    const float* gk  = (const float*)d_in[8];
    const float* btk = (const float*)d_in[9];
    const float* wv  = (const float*)d_in[10];
    const float* bv  = (const float*)d_in[11];
    const float* gv  = (const float*)d_in[12];
    const float* btv = (const float*)d_in[13];
    const float* wo  = (const float*)d_in[14];
    const float* bo  = (const float*)d_in[15];
    const float* go  = (const float*)d_in[16];
    const float* bto = (const float*)d_in[17];
    const float* lw  = (const float*)d_in[18];
    const float* lb  = (const float*)d_in[19];
    float* out = (float*)d_out;

    float *pBias, *pSte, *pY, *pAtt, *pOpre, *pStats, *pScale, *pShift;
    __nv_bfloat16 *pWb1, *pWb2, *pWbo;
    cudaGetSymbolAddress((void**)&pWb1,   g_Wb1);
    cudaGetSymbolAddress((void**)&pWb2,   g_Wb2);
    cudaGetSymbolAddress((void**)&pWbo,   g_Wbo);
    cudaGetSymbolAddress((void**)&pBias,  g_bias);
    cudaGetSymbolAddress((void**)&pSte,   g_ste);
    cudaGetSymbolAddress((void**)&pY,     g_y);
    cudaGetSymbolAddress((void**)&pAtt,   g_attout);
    cudaGetSymbolAddress((void**)&pOpre,  g_opre);
    cudaGetSymbolAddress((void**)&pStats, g_stats);
    cudaGetSymbolAddress((void**)&pScale, g_bnscale);
    cudaGetSymbolAddress((void**)&pShift, g_bnshift);

    constexpr int SM_QKV = hg_smem<true>();    // 207,872
    constexpr int SM_PLN = hg_smem<false>();   // 140,288

    cudaFuncSetAttribute((const void*)hgemm_kernel<3, false, false, true,  false>,
                         cudaFuncAttributeMaxDynamicSharedMemorySize, SM_PLN);
    cudaFuncSetAttribute((const void*)hgemm_kernel<3, true,  true,  false, true>,
                         cudaFuncAttributeMaxDynamicSharedMemorySize, SM_QKV);
    cudaFuncSetAttribute((const void*)hgemm_kernel<1, false, true,  true,  false>,
                         cudaFuncAttributeMaxDynamicSharedMemorySize, SM_PLN);

    const float invM = 1.0f / (float)M1;

    zero_stats_kernel<<<1, 1024>>>();
    pack_qkv_kernel<<<(3 * 128 * 128 + 255) / 256, 256>>>(wq, bq, wk, bk, wv, bv);
    pack_wo_kernel<<<64, 256>>>(wo);

    // STE part of QKV FC: [32768,128] @ W2 + bias -> g_ste
    hgemm_kernel<3, false, false, true, false><<<M0 / 128, 256, SM_PLN>>>(
        STE, pWb2, pBias, nullptr, pSte, nullptr, 0);

    // X part + STE add + stats: [229376,128] @ W1 -> g_y
    hgemm_kernel<3, true, true, false, true><<<M1 / 128, 256, SM_QKV>>>(
        X, pWb1, nullptr, pSte, pY, pStats, 0);

    bn_params_kernel<<<1, 128>>>(pStats,   0, gq, btq, pScale, pShift,   0, invM);
    bn_params_kernel<<<1, 128>>>(pStats, 128, gk, btk, pScale, pShift, 128, invM);
    bn_params_kernel<<<1, 128>>>(pStats, 256, gv, btv, pScale, pShift, 256, invM);

    attn_kernel<<<M0, 128>>>(pY, pScale, pShift, pAtt);

    // O FC: [229376,128] @ wo + bias + stats -> g_opre
    hgemm_kernel<1, false, true, true, false><<<M1 / 128, 256, SM_PLN>>>(
        pAtt, pWbo, bo, nullptr, pOpre, pStats, 384);

    bn_params_kernel<<<1, 128>>>(pStats, 384, go, bto, pScale, pShift, 384, invM);

    final_kernel<<<(BB * NN * DD + 255) / 256, 256>>>(pOpre, lw, lb, pScale + 384, pShift + 384, out);
}